// round 14
// baseline (speedup 1.0000x reference)
#include <cuda_runtime.h>
#include <cuda_fp16.h>

#define N_NODES 50000
#define OUT_DIM 128
#define NNZ_X 800000
#define N_EDGES 1600000
#define CAP_X 48     // Poisson(16): P(row >= 48) * 50k ~ 5e-5, guarded
#define HSZ (N_NODES * OUT_DIM)

// ---- persistent scratch (__device__ globals; zero-initialized at load) ----
__device__ __half g_hh[HSZ];          // 12.8 MB intermediate h (fp16)
// split fp16 output accumulators, interleaved per row: [row][2][128] halfs
__device__ __half g_outh[2 * HSZ];    // 25.6 MB; zero at entry (final self-cleans)
__device__ int    g_xcnt[N_NODES];    // self-cleaning counters (hop1 resets)
__device__ int2   g_bx[N_NODES * CAP_X];  // 19.2 MB X buckets {col, fp32 val bits}

__device__ __forceinline__ void red_add_v2h2(__half* ptr, unsigned a, unsigned b) {
    asm volatile("red.global.add.noftz.v2.f16x2 [%0], {%1,%2};"
                 :: "l"(ptr), "r"(a), "r"(b) : "memory");
}

// ---- 1: scatter X into fixed-capacity row buckets (exact fp32 values) ----
__global__ void scatter_x_kernel(const int4* __restrict__ x_rows4,
                                 const int4* __restrict__ x_cols4,
                                 const float4* __restrict__ x_vals4,
                                 const float4* __restrict__ noise4) {
    int idx = blockIdx.x * blockDim.x + threadIdx.x;
    int stride = gridDim.x * blockDim.x;
    for (int i = idx; i < NNZ_X / 4; i += stride) {
        int4 r = x_rows4[i];
        int4 c = x_cols4[i];
        float4 v = x_vals4[i];
        float4 n = noise4[i];
        v.x *= floorf(1.0f + n.x);   // keep_prob=1 -> mask==1 (faithful to ref)
        v.y *= floorf(1.0f + n.y);
        v.z *= floorf(1.0f + n.z);
        v.w *= floorf(1.0f + n.w);
        int p0 = atomicAdd(&g_xcnt[r.x], 1);
        int p1 = atomicAdd(&g_xcnt[r.y], 1);
        int p2 = atomicAdd(&g_xcnt[r.z], 1);
        int p3 = atomicAdd(&g_xcnt[r.w], 1);
        if (p0 < CAP_X) g_bx[r.x * CAP_X + p0] = make_int2(c.x, __float_as_int(v.x));
        if (p1 < CAP_X) g_bx[r.y * CAP_X + p1] = make_int2(c.y, __float_as_int(v.y));
        if (p2 < CAP_X) g_bx[r.z * CAP_X + p2] = make_int2(c.z, __float_as_int(v.z));
        if (p3 < CAP_X) g_bx[r.w * CAP_X + p3] = make_int2(c.w, __float_as_int(v.w));
    }
}

// ---- 2: hop1  h[row] = sum v * W[col]  (warp per row, predicated x4, fp16 out) ----
__global__ void hop1_kernel(const float4* __restrict__ W4) {
    int row = (blockIdx.x * blockDim.x + threadIdx.x) >> 5;
    int lane = threadIdx.x & 31;
    if (row >= N_NODES) return;
    int n = g_xcnt[row];                  // broadcast load
    __syncwarp();
    if (lane == 0) g_xcnt[row] = 0;       // self-clean for next replay
    n = min(n, CAP_X);
    const int2* __restrict__ e = g_bx + row * CAP_X;
    float4 acc = make_float4(0.f, 0.f, 0.f, 0.f);
    for (int i = 0; i < n; i += 4) {
        int2 p[4];
        float4 w[4];
        float vv[4];
#pragma unroll
        for (int k = 0; k < 4; k++) {
            int j = i + k;
            p[k] = e[j < n ? j : n - 1];          // clamp (n>0 inside loop)
            vv[k] = (j < n) ? __int_as_float(p[k].y) : 0.f;
        }
#pragma unroll
        for (int k = 0; k < 4; k++) w[k] = W4[p[k].x * 32 + lane];
#pragma unroll
        for (int k = 0; k < 4; k++) {
            acc.x += vv[k] * w[k].x;
            acc.y += vv[k] * w[k].y;
            acc.z += vv[k] * w[k].z;
            acc.w += vv[k] * w[k].w;
        }
    }
    __half2 lo = __floats2half2_rn(acc.x, acc.y);
    __half2 hi = __floats2half2_rn(acc.z, acc.w);
    uint2 u;
    u.x = *reinterpret_cast<unsigned*>(&lo);
    u.y = *reinterpret_cast<unsigned*>(&hi);
    reinterpret_cast<uint2*>(g_hh)[row * 32 + lane] = u;  // all rows written (0 if empty)
}

// ---- 3: hop2  outh[row][par] += w * h_fp16[col]  (edge-parallel, split fp16 RED) ----
__global__ void hop2_red_kernel(const int* __restrict__ rows,
                                const int* __restrict__ cols,
                                const float* __restrict__ wvals) {
    int gw = (blockIdx.x * blockDim.x + threadIdx.x) >> 5;
    int lane = threadIdx.x & 31;
    int base = gw * 8;
    if (base >= N_EDGES) return;
    const uint2* __restrict__ h2 = reinterpret_cast<const uint2*>(g_hh);
    int   r[8], c[8];
    float v[8];
    uint2 u[8];
#pragma unroll
    for (int k = 0; k < 8; k++) {
        int e = base + k;
        r[k] = rows[e];          // broadcast loads (L1)
        c[k] = cols[e];
        v[k] = wvals[e];
    }
#pragma unroll
    for (int k = 0; k < 8; k++) u[k] = h2[c[k] * 32 + lane];   // 8B/lane gather
#pragma unroll
    for (int k = 0; k < 8; k++) {
        __half2 lo = *reinterpret_cast<__half2*>(&u[k].x);
        __half2 hi = *reinterpret_cast<__half2*>(&u[k].y);
        float2 f0 = __half22float2(lo);
        float2 f1 = __half22float2(hi);
        __half2 a = __floats2half2_rn(v[k] * f0.x, v[k] * f0.y);
        __half2 b = __floats2half2_rn(v[k] * f1.x, v[k] * f1.y);
        // interleaved split: one 32-bit offset off a single base pointer
        unsigned off = (unsigned)r[k] * 256u + ((k & 1) << 7) + lane * 4;
        red_add_v2h2(g_outh + off,
                     *reinterpret_cast<unsigned*>(&a),
                     *reinterpret_cast<unsigned*>(&b));
    }
}

// ---- 4: combine split accumulators -> fp32 out + relu; self-clean to zero ----
__global__ void final_kernel(float4* __restrict__ out4) {
    const int total = HSZ / 4;                    // 1.6M float4 outputs
    int idx = blockIdx.x * blockDim.x + threadIdx.x;
    int stride = gridDim.x * blockDim.x;
    const uint2 z2 = make_uint2(0u, 0u);
    for (int i = idx; i < total; i += stride) {
        int row = i >> 5;
        int c = i & 31;
        uint2* pa = reinterpret_cast<uint2*>(g_outh + (size_t)row * 256) + c;
        uint2* pb = reinterpret_cast<uint2*>(g_outh + (size_t)row * 256 + 128) + c;
        uint2 ua = *pa;
        uint2 ub = *pb;
        *pa = z2;                                 // self-clean for next replay
        *pb = z2;
        float2 a0 = __half22float2(*reinterpret_cast<__half2*>(&ua.x));
        float2 a1 = __half22float2(*reinterpret_cast<__half2*>(&ua.y));
        float2 b0 = __half22float2(*reinterpret_cast<__half2*>(&ub.x));
        float2 b1 = __half22float2(*reinterpret_cast<__half2*>(&ub.y));
        float4 t;
        t.x = fmaxf(a0.x + b0.x, 0.f);
        t.y = fmaxf(a0.y + b0.y, 0.f);
        t.z = fmaxf(a1.x + b1.x, 0.f);
        t.w = fmaxf(a1.y + b1.y, 0.f);
        out4[i] = t;
    }
}

extern "C" void kernel_launch(void* const* d_in, const int* in_sizes, int n_in,
                              void* d_out, int out_size) {
    const int*   x_rows   = (const int*)d_in[0];
    const int*   x_cols   = (const int*)d_in[1];
    const float* x_vals   = (const float*)d_in[2];
    const float* noise    = (const float*)d_in[3];
    const int*   adj_rows = (const int*)d_in[4];
    const int*   adj_cols = (const int*)d_in[5];
    const float* adj_vals = (const float*)d_in[6];
    const float* W        = (const float*)d_in[7];
    float* out = (float*)d_out;

    scatter_x_kernel<<<800, 256>>>((const int4*)x_rows, (const int4*)x_cols,
                                   (const float4*)x_vals, (const float4*)noise);

    hop1_kernel<<<(N_NODES * 32 + 255) / 256, 256>>>(reinterpret_cast<const float4*>(W));

    // edge-parallel: warp per 8 edges -> 200k warps -> 25k blocks
    hop2_red_kernel<<<(N_EDGES / 8 * 32 + 255) / 256, 256>>>(adj_rows, adj_cols, adj_vals);

    final_kernel<<<1184, 256>>>(reinterpret_cast<float4*>(out));
}

// round 15
// speedup vs baseline: 1.1399x; 1.1399x over previous
#include <cuda_runtime.h>
#include <cuda_fp16.h>

#define N_NODES 50000
#define OUT_DIM 128
#define NNZ_X 800000
#define N_EDGES 1600000
#define CAP_X 48     // Poisson(16): P(row >= 48) * 50k ~ 5e-5, guarded
#define HSZ (N_NODES * OUT_DIM)

// ---- persistent scratch (__device__ globals; zero-initialized at load) ----
__device__ __half g_hh[HSZ];          // 12.8 MB intermediate h (fp16)
// split fp16 output accumulators, interleaved per row: [row][2][128] halfs
__device__ __half g_outh[2 * HSZ];    // 25.6 MB; zeroed inside scatter_x each call
__device__ int    g_xcnt[N_NODES];    // self-cleaning counters (hop1 resets)
__device__ int2   g_bx[N_NODES * CAP_X];  // 19.2 MB X buckets {col, fp32 val bits}

__device__ __forceinline__ void red_add_v2h2(__half* ptr, unsigned a, unsigned b) {
    asm volatile("red.global.add.noftz.v2.f16x2 [%0], {%1,%2};"
                 :: "l"(ptr), "r"(a), "r"(b) : "memory");
}

// ---- 1: scatter X into buckets + zero g_outh (fused: scatter is issue-idle) ----
__global__ void scatter_x_kernel(const int4* __restrict__ x_rows4,
                                 const int4* __restrict__ x_cols4,
                                 const float4* __restrict__ x_vals4,
                                 const float4* __restrict__ noise4) {
    int idx = blockIdx.x * blockDim.x + threadIdx.x;
    int stride = gridDim.x * blockDim.x;

    // fused zero of the fp16 output accumulators (hidden under atomic latency)
    {
        float4* o4 = reinterpret_cast<float4*>(g_outh);
        const float4 z = make_float4(0.f, 0.f, 0.f, 0.f);
        const int ztotal = 2 * HSZ * 2 / 16;      // 1.6M float4
        for (int i = idx; i < ztotal; i += stride) o4[i] = z;
    }

    for (int i = idx; i < NNZ_X / 4; i += stride) {
        int4 r = x_rows4[i];
        int4 c = x_cols4[i];
        float4 v = x_vals4[i];
        float4 n = noise4[i];
        v.x *= floorf(1.0f + n.x);   // keep_prob=1 -> mask==1 (faithful to ref)
        v.y *= floorf(1.0f + n.y);
        v.z *= floorf(1.0f + n.z);
        v.w *= floorf(1.0f + n.w);
        int p0 = atomicAdd(&g_xcnt[r.x], 1);
        int p1 = atomicAdd(&g_xcnt[r.y], 1);
        int p2 = atomicAdd(&g_xcnt[r.z], 1);
        int p3 = atomicAdd(&g_xcnt[r.w], 1);
        if (p0 < CAP_X) g_bx[r.x * CAP_X + p0] = make_int2(c.x, __float_as_int(v.x));
        if (p1 < CAP_X) g_bx[r.y * CAP_X + p1] = make_int2(c.y, __float_as_int(v.y));
        if (p2 < CAP_X) g_bx[r.z * CAP_X + p2] = make_int2(c.z, __float_as_int(v.z));
        if (p3 < CAP_X) g_bx[r.w * CAP_X + p3] = make_int2(c.w, __float_as_int(v.w));
    }
}

// ---- 2: hop1  h[row] = sum v * W[col]  (warp per row, predicated x4, fp16 out) ----
__global__ void hop1_kernel(const float4* __restrict__ W4) {
    int row = (blockIdx.x * blockDim.x + threadIdx.x) >> 5;
    int lane = threadIdx.x & 31;
    if (row >= N_NODES) return;
    int n = g_xcnt[row];                  // broadcast load
    __syncwarp();
    if (lane == 0) g_xcnt[row] = 0;       // self-clean for next replay
    n = min(n, CAP_X);
    const int2* __restrict__ e = g_bx + row * CAP_X;
    float4 acc = make_float4(0.f, 0.f, 0.f, 0.f);
    for (int i = 0; i < n; i += 4) {
        int2 p[4];
        float4 w[4];
        float vv[4];
#pragma unroll
        for (int k = 0; k < 4; k++) {
            int j = i + k;
            p[k] = e[j < n ? j : n - 1];          // clamp (n>0 inside loop)
            vv[k] = (j < n) ? __int_as_float(p[k].y) : 0.f;
        }
#pragma unroll
        for (int k = 0; k < 4; k++) w[k] = W4[p[k].x * 32 + lane];
#pragma unroll
        for (int k = 0; k < 4; k++) {
            acc.x += vv[k] * w[k].x;
            acc.y += vv[k] * w[k].y;
            acc.z += vv[k] * w[k].z;
            acc.w += vv[k] * w[k].w;
        }
    }
    __half2 lo = __floats2half2_rn(acc.x, acc.y);
    __half2 hi = __floats2half2_rn(acc.z, acc.w);
    uint2 u;
    u.x = *reinterpret_cast<unsigned*>(&lo);
    u.y = *reinterpret_cast<unsigned*>(&hi);
    reinterpret_cast<uint2*>(g_hh)[row * 32 + lane] = u;  // all rows written (0 if empty)
}

// ---- 3: hop2  outh[row][par] += w * h_fp16[col]  (edge-parallel, split fp16 RED) ----
__global__ void hop2_red_kernel(const int* __restrict__ rows,
                                const int* __restrict__ cols,
                                const float* __restrict__ wvals) {
    int gw = (blockIdx.x * blockDim.x + threadIdx.x) >> 5;
    int lane = threadIdx.x & 31;
    int base = gw * 8;
    if (base >= N_EDGES) return;
    const uint2* __restrict__ h2 = reinterpret_cast<const uint2*>(g_hh);
    int   r[8], c[8];
    float v[8];
    uint2 u[8];
#pragma unroll
    for (int k = 0; k < 8; k++) {
        int e = base + k;
        r[k] = rows[e];          // broadcast loads (L1)
        c[k] = cols[e];
        v[k] = wvals[e];
    }
#pragma unroll
    for (int k = 0; k < 8; k++) u[k] = h2[c[k] * 32 + lane];   // 8B/lane gather
#pragma unroll
    for (int k = 0; k < 8; k++) {
        __half2 lo = *reinterpret_cast<__half2*>(&u[k].x);
        __half2 hi = *reinterpret_cast<__half2*>(&u[k].y);
        float2 f0 = __half22float2(lo);
        float2 f1 = __half22float2(hi);
        __half2 a = __floats2half2_rn(v[k] * f0.x, v[k] * f0.y);
        __half2 b = __floats2half2_rn(v[k] * f1.x, v[k] * f1.y);
        // interleaved split: one 32-bit offset off a single base pointer
        unsigned off = (unsigned)r[k] * 256u + ((k & 1) << 7) + lane * 4;
        red_add_v2h2(g_outh + off,
                     *reinterpret_cast<unsigned*>(&a),
                     *reinterpret_cast<unsigned*>(&b));
    }
}

// ---- 4: combine split accumulators -> fp32 out + relu (pure streaming pass) ----
__global__ void final_kernel(float4* __restrict__ out4) {
    const int total = HSZ / 4;                    // 1.6M float4 outputs
    int idx = blockIdx.x * blockDim.x + threadIdx.x;
    int stride = gridDim.x * blockDim.x;
    for (int i = idx; i < total; i += stride) {
        int row = i >> 5;
        int c = i & 31;
        const uint2* pa = reinterpret_cast<const uint2*>(g_outh + (size_t)row * 256) + c;
        const uint2* pb = reinterpret_cast<const uint2*>(g_outh + (size_t)row * 256 + 128) + c;
        uint2 ua = *pa;
        uint2 ub = *pb;
        float2 a0 = __half22float2(*reinterpret_cast<const __half2*>(&ua.x));
        float2 a1 = __half22float2(*reinterpret_cast<const __half2*>(&ua.y));
        float2 b0 = __half22float2(*reinterpret_cast<const __half2*>(&ub.x));
        float2 b1 = __half22float2(*reinterpret_cast<const __half2*>(&ub.y));
        float4 t;
        t.x = fmaxf(a0.x + b0.x, 0.f);
        t.y = fmaxf(a0.y + b0.y, 0.f);
        t.z = fmaxf(a1.x + b1.x, 0.f);
        t.w = fmaxf(a1.y + b1.y, 0.f);
        out4[i] = t;
    }
}

extern "C" void kernel_launch(void* const* d_in, const int* in_sizes, int n_in,
                              void* d_out, int out_size) {
    const int*   x_rows   = (const int*)d_in[0];
    const int*   x_cols   = (const int*)d_in[1];
    const float* x_vals   = (const float*)d_in[2];
    const float* noise    = (const float*)d_in[3];
    const int*   adj_rows = (const int*)d_in[4];
    const int*   adj_cols = (const int*)d_in[5];
    const float* adj_vals = (const float*)d_in[6];
    const float* W        = (const float*)d_in[7];
    float* out = (float*)d_out;

    scatter_x_kernel<<<1184, 256>>>((const int4*)x_rows, (const int4*)x_cols,
                                    (const float4*)x_vals, (const float4*)noise);

    hop1_kernel<<<(N_NODES * 32 + 255) / 256, 256>>>(reinterpret_cast<const float4*>(W));

    // edge-parallel: warp per 8 edges -> 200k warps -> 25k blocks
    hop2_red_kernel<<<(N_EDGES / 8 * 32 + 255) / 256, 256>>>(adj_rows, adj_cols, adj_vals);

    final_kernel<<<1184, 256>>>(reinterpret_cast<float4*>(out));
}

// round 16
// speedup vs baseline: 1.2151x; 1.0660x over previous
#include <cuda_runtime.h>
#include <cuda_fp16.h>

#define N_NODES 50000
#define OUT_DIM 128
#define NNZ_X 800000
#define N_EDGES 1600000
#define CAP_X 48     // Poisson(16): P(row >= 48) * 50k ~ 5e-5, guarded
#define HSZ (N_NODES * OUT_DIM)

// ---- persistent scratch (__device__ globals; zero-initialized at load) ----
__device__ __half g_hh[HSZ];          // 12.8 MB intermediate h (fp16)
// split fp16 output accumulators, interleaved per row: [row][2][128] halfs
__device__ __half g_outh[2 * HSZ];    // 25.6 MB; zeroed inside scatter_x each call
__device__ int    g_xcnt[N_NODES];    // self-cleaning counters (hop1 resets)
__device__ int2   g_bx[N_NODES * CAP_X];  // 19.2 MB X buckets {col, fp32 val bits}

__device__ __forceinline__ void red_add_v2h2(__half* ptr, unsigned a, unsigned b) {
    asm volatile("red.global.add.noftz.v2.f16x2 [%0], {%1,%2};"
                 :: "l"(ptr), "r"(a), "r"(b) : "memory");
}

// ---- 1: scatter X into buckets + zero g_outh (fused: scatter is issue-idle) ----
__global__ void scatter_x_kernel(const int4* __restrict__ x_rows4,
                                 const int4* __restrict__ x_cols4,
                                 const float4* __restrict__ x_vals4,
                                 const float4* __restrict__ noise4) {
    int idx = blockIdx.x * blockDim.x + threadIdx.x;
    int stride = gridDim.x * blockDim.x;

    // fused zero of the fp16 output accumulators (hidden under atomic latency)
    {
        float4* o4 = reinterpret_cast<float4*>(g_outh);
        const float4 z = make_float4(0.f, 0.f, 0.f, 0.f);
        const int ztotal = 2 * HSZ * 2 / 16;      // 1.6M float4
        for (int i = idx; i < ztotal; i += stride) o4[i] = z;
    }

    for (int i = idx; i < NNZ_X / 4; i += stride) {
        int4 r = x_rows4[i];
        int4 c = x_cols4[i];
        float4 v = x_vals4[i];
        float4 n = noise4[i];
        v.x *= floorf(1.0f + n.x);   // keep_prob=1 -> mask==1 (faithful to ref)
        v.y *= floorf(1.0f + n.y);
        v.z *= floorf(1.0f + n.z);
        v.w *= floorf(1.0f + n.w);
        int p0 = atomicAdd(&g_xcnt[r.x], 1);
        int p1 = atomicAdd(&g_xcnt[r.y], 1);
        int p2 = atomicAdd(&g_xcnt[r.z], 1);
        int p3 = atomicAdd(&g_xcnt[r.w], 1);
        if (p0 < CAP_X) g_bx[r.x * CAP_X + p0] = make_int2(c.x, __float_as_int(v.x));
        if (p1 < CAP_X) g_bx[r.y * CAP_X + p1] = make_int2(c.y, __float_as_int(v.y));
        if (p2 < CAP_X) g_bx[r.z * CAP_X + p2] = make_int2(c.z, __float_as_int(v.z));
        if (p3 < CAP_X) g_bx[r.w * CAP_X + p3] = make_int2(c.w, __float_as_int(v.w));
    }
}

// ---- 2: hop1  h[row] = sum v * W[col]  (warp per row, predicated x8, fp16 out) ----
__global__ void hop1_kernel(const float4* __restrict__ W4) {
    int row = (blockIdx.x * blockDim.x + threadIdx.x) >> 5;
    int lane = threadIdx.x & 31;
    if (row >= N_NODES) return;
    int n = g_xcnt[row];                  // broadcast load
    __syncwarp();
    if (lane == 0) g_xcnt[row] = 0;       // self-clean for next replay
    n = min(n, CAP_X);
    const int2* __restrict__ e = g_bx + row * CAP_X;
    float4 acc = make_float4(0.f, 0.f, 0.f, 0.f);
    for (int i = 0; i < n; i += 8) {
        int2 p[8];
        float4 w[8];
        float vv[8];
#pragma unroll
        for (int k = 0; k < 8; k++) {
            int j = i + k;
            p[k] = e[j < n ? j : n - 1];          // clamp (n>0 inside loop)
            vv[k] = (j < n) ? __int_as_float(p[k].y) : 0.f;
        }
#pragma unroll
        for (int k = 0; k < 8; k++) w[k] = W4[p[k].x * 32 + lane];
#pragma unroll
        for (int k = 0; k < 8; k++) {
            acc.x += vv[k] * w[k].x;
            acc.y += vv[k] * w[k].y;
            acc.z += vv[k] * w[k].z;
            acc.w += vv[k] * w[k].w;
        }
    }
    __half2 lo = __floats2half2_rn(acc.x, acc.y);
    __half2 hi = __floats2half2_rn(acc.z, acc.w);
    uint2 u;
    u.x = *reinterpret_cast<unsigned*>(&lo);
    u.y = *reinterpret_cast<unsigned*>(&hi);
    reinterpret_cast<uint2*>(g_hh)[row * 32 + lane] = u;  // all rows written (0 if empty)
}

// ---- 3: hop2  outh[row][par] += w * h_fp16[col]  (edge-parallel, split fp16 RED) ----
__global__ void hop2_red_kernel(const int* __restrict__ rows,
                                const int* __restrict__ cols,
                                const float* __restrict__ wvals) {
    int gw = (blockIdx.x * blockDim.x + threadIdx.x) >> 5;
    int lane = threadIdx.x & 31;
    int base = gw * 8;
    if (base >= N_EDGES) return;
    const uint2* __restrict__ h2 = reinterpret_cast<const uint2*>(g_hh);
    int   r[8], c[8];
    float v[8];
    uint2 u[8];
#pragma unroll
    for (int k = 0; k < 8; k++) {
        int e = base + k;
        r[k] = rows[e];          // broadcast loads (L1)
        c[k] = cols[e];
        v[k] = wvals[e];
    }
#pragma unroll
    for (int k = 0; k < 8; k++) u[k] = h2[c[k] * 32 + lane];   // 8B/lane gather
#pragma unroll
    for (int k = 0; k < 8; k++) {
        __half2 lo = *reinterpret_cast<__half2*>(&u[k].x);
        __half2 hi = *reinterpret_cast<__half2*>(&u[k].y);
        float2 f0 = __half22float2(lo);
        float2 f1 = __half22float2(hi);
        __half2 a = __floats2half2_rn(v[k] * f0.x, v[k] * f0.y);
        __half2 b = __floats2half2_rn(v[k] * f1.x, v[k] * f1.y);
        // interleaved split: one 32-bit offset off a single base pointer
        unsigned off = (unsigned)r[k] * 256u + ((k & 1) << 7) + lane * 4;
        red_add_v2h2(g_outh + off,
                     *reinterpret_cast<unsigned*>(&a),
                     *reinterpret_cast<unsigned*>(&b));
    }
}

// ---- 4: combine split accumulators -> fp32 out + relu (pure streaming pass) ----
__global__ void final_kernel(float4* __restrict__ out4) {
    const int total = HSZ / 4;                    // 1.6M float4 outputs
    int idx = blockIdx.x * blockDim.x + threadIdx.x;
    int stride = gridDim.x * blockDim.x;
    for (int i = idx; i < total; i += stride) {
        int row = i >> 5;
        int c = i & 31;
        const uint2* pa = reinterpret_cast<const uint2*>(g_outh + (size_t)row * 256) + c;
        const uint2* pb = reinterpret_cast<const uint2*>(g_outh + (size_t)row * 256 + 128) + c;
        uint2 ua = *pa;
        uint2 ub = *pb;
        float2 a0 = __half22float2(*reinterpret_cast<const __half2*>(&ua.x));
        float2 a1 = __half22float2(*reinterpret_cast<const __half2*>(&ua.y));
        float2 b0 = __half22float2(*reinterpret_cast<const __half2*>(&ub.x));
        float2 b1 = __half22float2(*reinterpret_cast<const __half2*>(&ub.y));
        float4 t;
        t.x = fmaxf(a0.x + b0.x, 0.f);
        t.y = fmaxf(a0.y + b0.y, 0.f);
        t.z = fmaxf(a1.x + b1.x, 0.f);
        t.w = fmaxf(a1.y + b1.y, 0.f);
        out4[i] = t;
    }
}

extern "C" void kernel_launch(void* const* d_in, const int* in_sizes, int n_in,
                              void* d_out, int out_size) {
    const int*   x_rows   = (const int*)d_in[0];
    const int*   x_cols   = (const int*)d_in[1];
    const float* x_vals   = (const float*)d_in[2];
    const float* noise    = (const float*)d_in[3];
    const int*   adj_rows = (const int*)d_in[4];
    const int*   adj_cols = (const int*)d_in[5];
    const float* adj_vals = (const float*)d_in[6];
    const float* W        = (const float*)d_in[7];
    float* out = (float*)d_out;

    scatter_x_kernel<<<1184, 256>>>((const int4*)x_rows, (const int4*)x_cols,
                                    (const float4*)x_vals, (const float4*)noise);

    hop1_kernel<<<(N_NODES * 32 + 255) / 256, 256>>>(reinterpret_cast<const float4*>(W));

    // edge-parallel: warp per 8 edges -> 200k warps -> 12.5k blocks of 512
    hop2_red_kernel<<<(N_EDGES / 8 * 32 + 511) / 512, 512>>>(adj_rows, adj_cols, adj_vals);

    final_kernel<<<1184, 256>>>(reinterpret_cast<float4*>(out));
}